// round 3
// baseline (speedup 1.0000x reference)
#include <cuda_runtime.h>
#include <cstdint>

// Problem constants
#define NN 200000
#define D  128
#define P  4096
#define R  4
#define T  3
#define K  16

// ---------------------------------------------------------------------------
// Scratch (static __device__ — no runtime allocation)
// ---------------------------------------------------------------------------
__device__ float g_u[T * D];        // u_t = W_phi[t] @ zn
__device__ float g_v[T * D];        // v_t = W_phi[t] @ zs
__device__ float g_bias2[D];        // 2 * sum_r W_beta_b[r][e]
__device__ float g_es[P * 2];       // e_s per (p,s)
__device__ float g_g[P * R * D];    // sum_s h_agg[p,s,r,:]

// ---------------------------------------------------------------------------
// Kernel 1: prep — u, v vectors and bias2. grid=4 blocks x 128 threads.
// ---------------------------------------------------------------------------
__global__ void prep_kernel(const float* __restrict__ W_phi,
                            const float* __restrict__ W_zeta,
                            const float* __restrict__ W_beta_b) {
    int b = blockIdx.x;
    int tid = threadIdx.x;
    if (b < T) {
        // u[b][tid] = sum_e W_phi[b][tid][e] * zn[e]; v likewise with zs
        const float* wrow = W_phi + (b * D + tid) * D;
        float au = 0.f, av = 0.f;
#pragma unroll 8
        for (int e = 0; e < D; e++) {
            float w = wrow[e];
            au = fmaf(w, W_zeta[e], au);
            av = fmaf(w, W_zeta[D + e], av);
        }
        g_u[b * D + tid] = au;
        g_v[b * D + tid] = av;
    } else {
        float s = 0.f;
#pragma unroll
        for (int r = 0; r < R; r++) s += W_beta_b[r * D + tid];
        g_bias2[tid] = 2.f * s;
    }
}

// ---------------------------------------------------------------------------
// Kernel 2: e_s per (p,s). One warp per pair-slot. grid=2048 x 128.
// ---------------------------------------------------------------------------
__global__ void es_kernel(const float* __restrict__ x,
                          const int* __restrict__ node_pairs,
                          const int* __restrict__ types) {
    int tid = threadIdx.x;
    int lane = tid & 31;
    int gw = blockIdx.x * 4 + (tid >> 5);   // ps index, 0..8191
    int node = node_pairs[gw];
    int t = types[node];
    const float4 x4 = *(const float4*)(x + node * D + lane * 4);
    const float4 v4 = *(const float4*)(g_v + t * D + lane * 4);
    float part = x4.x * v4.x + x4.y * v4.y + x4.z * v4.z + x4.w * v4.w;
#pragma unroll
    for (int off = 16; off; off >>= 1)
        part += __shfl_xor_sync(0xffffffffu, part, off);
    if (lane == 0) g_es[gw] = part;
}

// ---------------------------------------------------------------------------
// Kernel 3: main — gather neighbors, attention softmax, aggregate.
// One block (128 thr = 4 warps) per (p,r); loop over s in {0,1}.
// Warp w owns neighbors k = 4w..4w+3; lane owns dims lane*4..lane*4+3.
// ---------------------------------------------------------------------------
__global__ __launch_bounds__(128) void main_kernel(
    const float* __restrict__ x,
    const int* __restrict__ types,
    const int* __restrict__ nbr,
    const float* __restrict__ dt) {

    int bx = blockIdx.x;
    int p = bx >> 2;
    int r = bx & 3;
    int tid = threadIdx.x;
    int w = tid >> 5;
    int lane = tid & 31;

    __shared__ int   s_nidx[K];
    __shared__ int   s_ty[K];
    __shared__ float s_edt[K];
    __shared__ float s_en[K];
    __shared__ float s_exp[K];
    __shared__ __align__(16) float s_h[4 * D];

    float gacc = 0.f;

#pragma unroll
    for (int s = 0; s < 2; s++) {
        int base = ((p * 2 + s) * R + r) * K;
        if (tid < K) {
            int ni = nbr[base + tid];
            s_nidx[tid] = ni;
            s_ty[tid]   = types[ni];
            s_edt[tid]  = __expf(-dt[base + tid]);
        }
        __syncthreads();

        // dot products e_n[k] for this warp's 4 neighbors
        float4 xv[4];
        float part[4];
#pragma unroll
        for (int j = 0; j < 4; j++) {
            int k = w * 4 + j;
            int ni = s_nidx[k];
            int t  = s_ty[k];
            xv[j] = *(const float4*)(x + ni * D + lane * 4);
            float4 u4 = *(const float4*)(g_u + t * D + lane * 4);
            part[j] = xv[j].x * u4.x + xv[j].y * u4.y +
                      xv[j].z * u4.z + xv[j].w * u4.w;
        }
#pragma unroll
        for (int off = 16; off; off >>= 1) {
#pragma unroll
            for (int j = 0; j < 4; j++)
                part[j] += __shfl_xor_sync(0xffffffffu, part[j], off);
        }
        if (lane == 0) {
#pragma unroll
            for (int j = 0; j < 4; j++) s_en[w * 4 + j] = part[j];
        }
        __syncthreads();

        // softmax over K=16 (no max-subtraction: |e| <= ~3, exp stays O(10))
        float es = g_es[p * 2 + s];
        if (tid < K)
            s_exp[tid] = __expf((s_en[tid] + es) * s_edt[tid]);
        __syncthreads();

        float sum = 0.f;
#pragma unroll
        for (int k = 0; k < K; k++) sum += s_exp[k];
        float inv = __fdividef(1.f, sum);

        // h_agg partial for this warp's 4 neighbors
        float4 h = make_float4(0.f, 0.f, 0.f, 0.f);
#pragma unroll
        for (int j = 0; j < 4; j++) {
            float a = s_exp[w * 4 + j] * inv;
            h.x = fmaf(a, xv[j].x, h.x);
            h.y = fmaf(a, xv[j].y, h.y);
            h.z = fmaf(a, xv[j].z, h.z);
            h.w = fmaf(a, xv[j].w, h.w);
        }
        *(float4*)(s_h + w * D + lane * 4) = h;
        __syncthreads();

        // combine 4 warps' partials; thread tid owns dim d = tid
        gacc += (s_h[tid] + s_h[D + tid]) + (s_h[2 * D + tid] + s_h[3 * D + tid]);
        __syncthreads();   // protect smem reuse for next s
    }

    g_g[(p * R + r) * D + tid] = gacc;
}

// ---------------------------------------------------------------------------
// Kernel 4: out[p,e] = sigmoid( 0.125*( sum_{i<512} g[p,i]*Wb[i,e] + bias2[e]) )
// 8 pairs per block, 128 threads (thread = column e), packed f32x2 FMA.
// grid = P/8 = 512 blocks.
// ---------------------------------------------------------------------------
#define PPB 8
__global__ __launch_bounds__(128) void out_kernel(
    const float* __restrict__ Wb,   // W_beta_w flattened: [R*D, D] = [512,128]
    float* __restrict__ out) {

    int p0 = blockIdx.x * PPB;
    int tid = threadIdx.x;

    __shared__ __align__(16) float sg[PPB * R * D];   // 16 KB
    for (int i = tid; i < PPB * R * D; i += 128)
        sg[i] = g_g[p0 * (R * D) + i];
    __syncthreads();

    unsigned long long acc2[PPB];
#pragma unroll
    for (int pp = 0; pp < PPB; pp++) acc2[pp] = 0ull;

#pragma unroll 4
    for (int i = 0; i < R * D; i += 2) {
        float w0 = Wb[i * D + tid];
        float w1 = Wb[(i + 1) * D + tid];
        unsigned long long wp;
        asm("mov.b64 %0, {%1, %2};" : "=l"(wp) : "f"(w0), "f"(w1));
#pragma unroll
        for (int pp = 0; pp < PPB; pp++) {
            float2 gp = *(const float2*)(sg + pp * (R * D) + i);
            unsigned long long gpk;
            asm("mov.b64 %0, {%1, %2};" : "=l"(gpk) : "f"(gp.x), "f"(gp.y));
            asm("fma.rn.f32x2 %0, %1, %2, %0;" : "+l"(acc2[pp]) : "l"(wp), "l"(gpk));
        }
    }

    float bias = g_bias2[tid];
#pragma unroll
    for (int pp = 0; pp < PPB; pp++) {
        float lo, hi;
        asm("mov.b64 {%0, %1}, %2;" : "=f"(lo), "=f"(hi) : "l"(acc2[pp]));
        float v = 0.125f * (lo + hi + bias);
        out[(p0 + pp) * D + tid] = __fdividef(1.f, 1.f + __expf(-v));
    }
}

// ---------------------------------------------------------------------------
// Launch
// ---------------------------------------------------------------------------
extern "C" void kernel_launch(void* const* d_in, const int* in_sizes, int n_in,
                              void* d_out, int out_size) {
    const float* node_embeds  = (const float*)d_in[0];
    const int*   node_pairs   = (const int*)d_in[1];
    const int*   node_type_ids= (const int*)d_in[2];
    const int*   neighbor_idx = (const int*)d_in[3];
    const float* delta_t      = (const float*)d_in[4];
    const float* W_phi        = (const float*)d_in[5];
    const float* W_zeta       = (const float*)d_in[6];
    const float* W_beta_w     = (const float*)d_in[7];
    const float* W_beta_b     = (const float*)d_in[8];
    float* out = (float*)d_out;

    prep_kernel<<<4, 128>>>(W_phi, W_zeta, W_beta_b);
    es_kernel<<<(P * 2) / 4, 128>>>(node_embeds, node_pairs, node_type_ids);
    main_kernel<<<P * R, 128>>>(node_embeds, node_type_ids, neighbor_idx, delta_t);
    out_kernel<<<P / PPB, 128>>>(W_beta_w, out);
}

// round 7
// speedup vs baseline: 1.1492x; 1.1492x over previous
#include <cuda_runtime.h>
#include <cstdint>

// Problem constants
#define NN 200000
#define D  128
#define P  4096
#define R  4
#define T  3
#define K  16

// ---------------------------------------------------------------------------
// Scratch (static __device__ — no runtime allocation)
// ---------------------------------------------------------------------------
__device__ __align__(16) float g_u[T * D];        // u_t = W_phi[t] @ zn
__device__ __align__(16) float g_v[T * D];        // v_t = W_phi[t] @ zs
__device__ __align__(16) float g_bias2[D];        // 2 * sum_r W_beta_b[r][e]
__device__ __align__(16) float g_es[P * 2];       // e_s per (p,s)
__device__ __align__(16) float g_g[P * R * D];    // sum_s h_agg[p,s,r,:]

// ---------------------------------------------------------------------------
// Kernel 1: prep — u, v vectors and bias2. grid=4 blocks x 128 threads.
// ---------------------------------------------------------------------------
__global__ void prep_kernel(const float* __restrict__ W_phi,
                            const float* __restrict__ W_zeta,
                            const float* __restrict__ W_beta_b) {
    int b = blockIdx.x;
    int tid = threadIdx.x;
    if (b < T) {
        const float* wrow = W_phi + (b * D + tid) * D;
        float au = 0.f, av = 0.f;
#pragma unroll 8
        for (int e = 0; e < D; e++) {
            float w = wrow[e];
            au = fmaf(w, W_zeta[e], au);
            av = fmaf(w, W_zeta[D + e], av);
        }
        g_u[b * D + tid] = au;
        g_v[b * D + tid] = av;
    } else {
        float s = 0.f;
#pragma unroll
        for (int r = 0; r < R; r++) s += W_beta_b[r * D + tid];
        g_bias2[tid] = 2.f * s;
    }
}

// ---------------------------------------------------------------------------
// Kernel 2: e_s per (p,s). One warp per pair-slot. grid=2048 x 128.
// ---------------------------------------------------------------------------
__global__ void es_kernel(const float* __restrict__ x,
                          const int* __restrict__ node_pairs,
                          const int* __restrict__ types) {
    int tid = threadIdx.x;
    int lane = tid & 31;
    int gw = blockIdx.x * 4 + (tid >> 5);   // ps index, 0..8191
    int node = node_pairs[gw];
    int t = types[node];
    const float4 x4 = *(const float4*)(x + node * D + lane * 4);
    const float4 v4 = *(const float4*)(g_v + t * D + lane * 4);
    float part = x4.x * v4.x + x4.y * v4.y + x4.z * v4.z + x4.w * v4.w;
#pragma unroll
    for (int off = 16; off; off >>= 1)
        part += __shfl_xor_sync(0xffffffffu, part, off);
    if (lane == 0) g_es[gw] = part;
}

// ---------------------------------------------------------------------------
// Kernel 3: main — gather neighbors, attention softmax, aggregate.
// One block (128 thr = 4 warps) per (p,r); loop s in {0,1}.
// Warp w owns neighbors k = 4w..4w+3; lane owns dims lane*4..lane*4+3.
// Barriers: 3 per block (exp-s0, exp-s1, h-s1) via double-buffered smem.
// ---------------------------------------------------------------------------
__global__ __launch_bounds__(128) void main_kernel(
    const float* __restrict__ x,
    const int* __restrict__ types,
    const int* __restrict__ nbr,
    const float* __restrict__ dt) {

    int bx = blockIdx.x;
    int p = bx >> 2;
    int r = bx & 3;
    int tid = threadIdx.x;
    int w = tid >> 5;
    int lane = tid & 31;

    __shared__ __align__(16) float s_exp[2][K];
    __shared__ __align__(16) float s_h[2][4 * D];

    // lanes 0..3 load this warp's neighbor idx/type/dt for BOTH s up front
    int base0 = ((p * 2 + 0) * R + r) * K + w * 4;
    int base1 = base0 + R * K;
    int ni0 = 0, ni1 = 0, ty0 = 0, ty1 = 0;
    float edt0 = 0.f, edt1 = 0.f;
    if (lane < 4) {
        ni0 = nbr[base0 + lane];
        ni1 = nbr[base1 + lane];
        ty0 = types[ni0];
        ty1 = types[ni1];
        edt0 = __expf(-dt[base0 + lane]);
        edt1 = __expf(-dt[base1 + lane]);
    }
    float es0 = g_es[p * 2];
    float es1 = g_es[p * 2 + 1];

    int nidx[2][4], nty[2][4];
#pragma unroll
    for (int j = 0; j < 4; j++) {
        nidx[0][j] = __shfl_sync(0xffffffffu, ni0, j);
        nidx[1][j] = __shfl_sync(0xffffffffu, ni1, j);
        nty[0][j]  = __shfl_sync(0xffffffffu, ty0, j);
        nty[1][j]  = __shfl_sync(0xffffffffu, ty1, j);
    }

#pragma unroll
    for (int s = 0; s < 2; s++) {
        float es  = (s == 0) ? es0  : es1;
        float edt = (s == 0) ? edt0 : edt1;

        // gather + dot
        float4 xv[4];
        float part[4];
#pragma unroll
        for (int j = 0; j < 4; j++) {
            int ni = nidx[s][j];
            int t  = nty[s][j];
            xv[j] = *(const float4*)(x + ni * D + lane * 4);
            float4 u4 = *(const float4*)(g_u + t * D + lane * 4);
            part[j] = xv[j].x * u4.x + xv[j].y * u4.y +
                      xv[j].z * u4.z + xv[j].w * u4.w;
        }
#pragma unroll
        for (int off = 16; off; off >>= 1) {
#pragma unroll
            for (int j = 0; j < 4; j++)
                part[j] += __shfl_xor_sync(0xffffffffu, part[j], off);
        }

        // lane j (<4) computes exp for its neighbor directly
        float mye = (lane == 0) ? part[0] :
                    (lane == 1) ? part[1] :
                    (lane == 2) ? part[2] : part[3];
        if (lane < 4)
            s_exp[s][w * 4 + lane] = __expf((mye + es) * edt);
        __syncthreads();                       // exp visible block-wide

        // softmax denominator + aggregate
        float4 q0 = *(const float4*)&s_exp[s][0];
        float4 q1 = *(const float4*)&s_exp[s][4];
        float4 q2 = *(const float4*)&s_exp[s][8];
        float4 q3 = *(const float4*)&s_exp[s][12];
        float sum = (q0.x + q0.y + q0.z + q0.w) + (q1.x + q1.y + q1.z + q1.w)
                  + (q2.x + q2.y + q2.z + q2.w) + (q3.x + q3.y + q3.z + q3.w);
        float inv = __fdividef(1.f, sum);
        float4 me = (w == 0) ? q0 : (w == 1) ? q1 : (w == 2) ? q2 : q3;
        float a0 = me.x * inv, a1 = me.y * inv, a2 = me.z * inv, a3 = me.w * inv;

        float4 h;
        h.x = a0 * xv[0].x; h.y = a0 * xv[0].y; h.z = a0 * xv[0].z; h.w = a0 * xv[0].w;
        h.x = fmaf(a1, xv[1].x, h.x); h.y = fmaf(a1, xv[1].y, h.y);
        h.z = fmaf(a1, xv[1].z, h.z); h.w = fmaf(a1, xv[1].w, h.w);
        h.x = fmaf(a2, xv[2].x, h.x); h.y = fmaf(a2, xv[2].y, h.y);
        h.z = fmaf(a2, xv[2].z, h.z); h.w = fmaf(a2, xv[2].w, h.w);
        h.x = fmaf(a3, xv[3].x, h.x); h.y = fmaf(a3, xv[3].y, h.y);
        h.z = fmaf(a3, xv[3].z, h.z); h.w = fmaf(a3, xv[3].w, h.w);
        *(float4*)(s_h[s] + w * D + lane * 4) = h;
    }
    __syncthreads();                           // all h partials visible

    float gacc = (s_h[0][tid]         + s_h[0][D + tid])
               + (s_h[0][2 * D + tid] + s_h[0][3 * D + tid])
               + (s_h[1][tid]         + s_h[1][D + tid])
               + (s_h[1][2 * D + tid] + s_h[1][3 * D + tid]);
    g_g[(p * R + r) * D + tid] = gacc;
}

// ---------------------------------------------------------------------------
// Kernel 4: out = sigmoid(0.125*(G[4096,512] @ Wb[512,128] + bias2))
// Register-tiled smem GEMM: block tile 32M x 64N, 128 threads,
// micro-tile 2M x 8N per thread, K staged in smem (TK=16) with reg prefetch.
// Packed fma.rn.f32x2 along N. grid = (4096/32)*(128/64) = 256 blocks.
// ---------------------------------------------------------------------------
#define OTM 32
#define OTN 64
#define OTK 16
#define NTILES ((R * D) / OTK)   // 32

__global__ __launch_bounds__(128) void out_kernel(
    const float* __restrict__ Wb,   // [512,128]
    float* __restrict__ out) {

    int bx = blockIdx.x;
    int mb = bx >> 1;
    int nb = bx & 1;
    int p0 = mb * OTM;
    int n_off = nb * OTN;
    int tid = threadIdx.x;

    int tm = (tid & 15) * 2;        // 2 rows
    int tn = (tid >> 4) * 8;        // 8 cols

    __shared__ __align__(16) float As[OTK][OTM];   // 2 KB
    __shared__ __align__(16) float Bs[OTK][OTN];   // 4 KB

    // fill-thread mapping
    int am = tid >> 2, ak = (tid & 3) * 4;         // A: row am, cols ak..ak+3
    int bk = tid >> 3, bn = (tid & 7) * 8;         // B: row bk, cols bn..bn+7
    const float* gA = g_g + (p0 + am) * (R * D) + ak;
    const float* gB = Wb + bk * D + n_off + bn;

    float4 pa  = *(const float4*)gA;
    float4 pb0 = *(const float4*)gB;
    float4 pb1 = *(const float4*)(gB + 4);

    unsigned long long acc[2][4];
#pragma unroll
    for (int i = 0; i < 2; i++)
#pragma unroll
        for (int j = 0; j < 4; j++) acc[i][j] = 0ull;

    for (int t = 0; t < NTILES; t++) {
        __syncthreads();   // previous compute done before overwrite
        As[ak + 0][am] = pa.x;
        As[ak + 1][am] = pa.y;
        As[ak + 2][am] = pa.z;
        As[ak + 3][am] = pa.w;
        *(float4*)&Bs[bk][bn]     = pb0;
        *(float4*)&Bs[bk][bn + 4] = pb1;
        __syncthreads();
        if (t + 1 < NTILES) {   // prefetch next tile, overlaps compute
            pa  = *(const float4*)(gA + (t + 1) * OTK);
            pb0 = *(const float4*)(gB + (t + 1) * OTK * D);
            pb1 = *(const float4*)(gB + (t + 1) * OTK * D + 4);
        }
#pragma unroll
        for (int k = 0; k < OTK; k++) {
            float2 a2 = *(const float2*)&As[k][tm];
            unsigned long long ap0, ap1;
            asm("mov.b64 %0, {%1, %2};" : "=l"(ap0) : "f"(a2.x), "f"(a2.x));
            asm("mov.b64 %0, {%1, %2};" : "=l"(ap1) : "f"(a2.y), "f"(a2.y));
            ulonglong2 b01 = *(const ulonglong2*)&Bs[k][tn];
            ulonglong2 b23 = *(const ulonglong2*)&Bs[k][tn + 4];
            asm("fma.rn.f32x2 %0, %1, %2, %0;" : "+l"(acc[0][0]) : "l"(ap0), "l"(b01.x));
            asm("fma.rn.f32x2 %0, %1, %2, %0;" : "+l"(acc[0][1]) : "l"(ap0), "l"(b01.y));
            asm("fma.rn.f32x2 %0, %1, %2, %0;" : "+l"(acc[0][2]) : "l"(ap0), "l"(b23.x));
            asm("fma.rn.f32x2 %0, %1, %2, %0;" : "+l"(acc[0][3]) : "l"(ap0), "l"(b23.y));
            asm("fma.rn.f32x2 %0, %1, %2, %0;" : "+l"(acc[1][0]) : "l"(ap1), "l"(b01.x));
            asm("fma.rn.f32x2 %0, %1, %2, %0;" : "+l"(acc[1][1]) : "l"(ap1), "l"(b01.y));
            asm("fma.rn.f32x2 %0, %1, %2, %0;" : "+l"(acc[1][2]) : "l"(ap1), "l"(b23.x));
            asm("fma.rn.f32x2 %0, %1, %2, %0;" : "+l"(acc[1][3]) : "l"(ap1), "l"(b23.y));
        }
    }

    // epilogue
    float4 bias0 = *(const float4*)&g_bias2[n_off + tn];
    float4 bias1 = *(const float4*)&g_bias2[n_off + tn + 4];
#pragma unroll
    for (int mi = 0; mi < 2; mi++) {
        float c[8];
#pragma unroll
        for (int j = 0; j < 4; j++) {
            float lo, hi;
            asm("mov.b64 {%0, %1}, %2;" : "=f"(lo), "=f"(hi) : "l"(acc[mi][j]));
            c[2 * j]     = lo;
            c[2 * j + 1] = hi;
        }
        float4 o0, o1;
        o0.x = 0.125f * (c[0] + bias0.x);
        o0.y = 0.125f * (c[1] + bias0.y);
        o0.z = 0.125f * (c[2] + bias0.z);
        o0.w = 0.125f * (c[3] + bias0.w);
        o1.x = 0.125f * (c[4] + bias1.x);
        o1.y = 0.125f * (c[5] + bias1.y);
        o1.z = 0.125f * (c[6] + bias1.z);
        o1.w = 0.125f * (c[7] + bias1.w);
        o0.x = __fdividef(1.f, 1.f + __expf(-o0.x));
        o0.y = __fdividef(1.f, 1.f + __expf(-o0.y));
        o0.z = __fdividef(1.f, 1.f + __expf(-o0.z));
        o0.w = __fdividef(1.f, 1.f + __expf(-o0.w));
        o1.x = __fdividef(1.f, 1.f + __expf(-o1.x));
        o1.y = __fdividef(1.f, 1.f + __expf(-o1.y));
        o1.z = __fdividef(1.f, 1.f + __expf(-o1.z));
        o1.w = __fdividef(1.f, 1.f + __expf(-o1.w));
        float* orow = out + (p0 + tm + mi) * D + n_off + tn;
        *(float4*)orow       = o0;
        *(float4*)(orow + 4) = o1;
    }
}

// ---------------------------------------------------------------------------
// Launch
// ---------------------------------------------------------------------------
extern "C" void kernel_launch(void* const* d_in, const int* in_sizes, int n_in,
                              void* d_out, int out_size) {
    const float* node_embeds   = (const float*)d_in[0];
    const int*   node_pairs    = (const int*)d_in[1];
    const int*   node_type_ids = (const int*)d_in[2];
    const int*   neighbor_idx  = (const int*)d_in[3];
    const float* delta_t       = (const float*)d_in[4];
    const float* W_phi         = (const float*)d_in[5];
    const float* W_zeta        = (const float*)d_in[6];
    const float* W_beta_w      = (const float*)d_in[7];
    const float* W_beta_b      = (const float*)d_in[8];
    float* out = (float*)d_out;

    prep_kernel<<<4, 128>>>(W_phi, W_zeta, W_beta_b);
    es_kernel<<<(P * 2) / 4, 128>>>(node_embeds, node_pairs, node_type_ids);
    main_kernel<<<P * R, 128>>>(node_embeds, node_type_ids, neighbor_idx, delta_t);
    out_kernel<<<(P / OTM) * (D / OTN), 128>>>(W_beta_w, out);
}

// round 8
// speedup vs baseline: 1.2631x; 1.0991x over previous
#include <cuda_runtime.h>
#include <cstdint>

// Problem constants
#define NN 200000
#define D  128
#define P  4096
#define R  4
#define T  3
#define K  16

// ---------------------------------------------------------------------------
// Scratch (static __device__ — no runtime allocation)
// ---------------------------------------------------------------------------
#define KSPLIT 8
#define PD (P * D)

__device__ __align__(16) float g_u[T * D];          // u_t = W_phi[t] @ zn
__device__ __align__(16) float g_v[T * D];          // v_t = W_phi[t] @ zs
__device__ __align__(16) float g_bias2[D];          // 2 * sum_r W_beta_b[r][e]
__device__ __align__(16) float g_es[P * 2];         // e_s per (p,s)
__device__ __align__(16) float g_g[P * R * D];      // sum_s h_agg[p,s,r,:]
__device__ __align__(16) float g_part[KSPLIT * PD]; // split-K partials (16.8 MB)

// ---------------------------------------------------------------------------
// Kernel 1: prep — u, v vectors and bias2. grid=4 blocks x 128 threads.
// ---------------------------------------------------------------------------
__global__ void prep_kernel(const float* __restrict__ W_phi,
                            const float* __restrict__ W_zeta,
                            const float* __restrict__ W_beta_b) {
    int b = blockIdx.x;
    int tid = threadIdx.x;
    if (b < T) {
        const float* wrow = W_phi + (b * D + tid) * D;
        float au = 0.f, av = 0.f;
#pragma unroll 8
        for (int e = 0; e < D; e++) {
            float w = wrow[e];
            au = fmaf(w, W_zeta[e], au);
            av = fmaf(w, W_zeta[D + e], av);
        }
        g_u[b * D + tid] = au;
        g_v[b * D + tid] = av;
    } else {
        float s = 0.f;
#pragma unroll
        for (int r = 0; r < R; r++) s += W_beta_b[r * D + tid];
        g_bias2[tid] = 2.f * s;
    }
}

// ---------------------------------------------------------------------------
// Kernel 2: e_s per (p,s). One warp per pair-slot. grid=2048 x 128.
// ---------------------------------------------------------------------------
__global__ void es_kernel(const float* __restrict__ x,
                          const int* __restrict__ node_pairs,
                          const int* __restrict__ types) {
    int tid = threadIdx.x;
    int lane = tid & 31;
    int gw = blockIdx.x * 4 + (tid >> 5);   // ps index, 0..8191
    int node = node_pairs[gw];
    int t = types[node];
    const float4 x4 = *(const float4*)(x + (size_t)node * D + lane * 4);
    const float4 v4 = *(const float4*)(g_v + t * D + lane * 4);
    float part = x4.x * v4.x + x4.y * v4.y + x4.z * v4.z + x4.w * v4.w;
#pragma unroll
    for (int off = 16; off; off >>= 1)
        part += __shfl_xor_sync(0xffffffffu, part, off);
    if (lane == 0) g_es[gw] = part;
}

// ---------------------------------------------------------------------------
// Kernel 3: main — gather + softmax + aggregate.
// Block = pair p (128 thr), warp w = relation r. NO cross-warp communication:
// warp handles all K=16 neighbors for (p, s, r); softmax normalization is
// deferred (aggregate with raw exp weights, scale by 1/sum at the end).
// One barrier total (stage u-table into smem). grid = 4096.
// ---------------------------------------------------------------------------
__global__ __launch_bounds__(128) void main_kernel(
    const float* __restrict__ x,
    const int* __restrict__ types,
    const int* __restrict__ nbr,
    const float* __restrict__ dt) {

    int p = blockIdx.x;
    int tid = threadIdx.x;
    int w = tid >> 5;       // r
    int lane = tid & 31;

    __shared__ __align__(16) float s_u[T * D];   // 1.5 KB
    s_u[tid]       = g_u[tid];
    s_u[tid + 128] = g_u[tid + 128];
    s_u[tid + 256] = g_u[tid + 256];
    __syncthreads();

    float4 hacc = make_float4(0.f, 0.f, 0.f, 0.f);
    int base0 = (p * 2 * R + w) * K;

#pragma unroll
    for (int s = 0; s < 2; s++) {
        int base = base0 + s * (R * K);

        int ni = 0, ty = 0;
        float edt = 0.f;
        if (lane < 16) {
            ni  = nbr[base + lane];
            edt = __expf(-dt[base + lane]);
            ty  = types[ni];
        }
        float es = g_es[p * 2 + s];

        float sum = 0.f;
        float4 hs = make_float4(0.f, 0.f, 0.f, 0.f);

#pragma unroll
        for (int b = 0; b < 2; b++) {        // two batches of 8 neighbors
            float4 xv[8];
#pragma unroll
            for (int j = 0; j < 8; j++) {
                int k = b * 8 + j;
                int nik = __shfl_sync(0xffffffffu, ni, k);
                xv[j] = *(const float4*)(x + (size_t)nik * D + lane * 4);
            }
#pragma unroll
            for (int j = 0; j < 8; j++) {
                int k = b * 8 + j;
                int tyk = __shfl_sync(0xffffffffu, ty, k);
                const float4 u4 = *(const float4*)&s_u[tyk * D + lane * 4];
                float d = xv[j].x * u4.x + xv[j].y * u4.y +
                          xv[j].z * u4.z + xv[j].w * u4.w;
#pragma unroll
                for (int off = 16; off; off >>= 1)
                    d += __shfl_xor_sync(0xffffffffu, d, off);
                float edtk = __shfl_sync(0xffffffffu, edt, k);
                float ex = __expf((d + es) * edtk);   // all lanes same value
                sum += ex;
                hs.x = fmaf(ex, xv[j].x, hs.x);
                hs.y = fmaf(ex, xv[j].y, hs.y);
                hs.z = fmaf(ex, xv[j].z, hs.z);
                hs.w = fmaf(ex, xv[j].w, hs.w);
            }
        }
        float inv = __fdividef(1.f, sum);
        hacc.x = fmaf(inv, hs.x, hacc.x);
        hacc.y = fmaf(inv, hs.y, hacc.y);
        hacc.z = fmaf(inv, hs.z, hacc.z);
        hacc.w = fmaf(inv, hs.w, hacc.w);
    }

    *(float4*)(g_g + (size_t)(p * R + w) * D + lane * 4) = hacc;
}

// ---------------------------------------------------------------------------
// Kernel 4: split-K GEMM partials. C_part[ks] = G[:, ks*64:(ks+1)*64] @ Wb[...]
// Block tile 64M x 128N, K=64 per block (two 32-k smem stages), 128 threads,
// micro-tile 8M x 8N (smem traffic: 1 B/FMA). grid = 64 Mtiles * 8 Kslices.
// ---------------------------------------------------------------------------
#define GKB 64
#define GKT 32
#define GM  64
#define GN  128

__global__ __launch_bounds__(128) void gemm_kernel(const float* __restrict__ Wb) {
    int bx = blockIdx.x;
    int mb = bx & 63;
    int ks = bx >> 6;
    int p0 = mb * GM;
    int kbase = ks * GKB;
    int tid = threadIdx.x;

    __shared__ __align__(16) float As[GKT][GM];   // 8 KB  (k-major, m contig)
    __shared__ __align__(16) float Bs[GKT][GN];   // 16 KB

    // fill mappings
    int am = tid >> 1;            // A row (0..63)
    int kh = (tid & 1) * 16;      // A k half (16 floats each)
    int bk = tid >> 2;            // B k row (0..31)
    int bn = (tid & 3) * 32;      // B col chunk (32 floats)

    // compute mapping: 8x16 thread grid, micro 8M x 8N
    int tm = (tid >> 4) * 8;
    int tn = (tid & 15) * 8;

    unsigned long long acc[8][4];
#pragma unroll
    for (int mi = 0; mi < 8; mi++)
#pragma unroll
        for (int j = 0; j < 4; j++) acc[mi][j] = 0ull;

#pragma unroll
    for (int t = 0; t < 2; t++) {
        int k0 = kbase + t * GKT;
        const float* ga = g_g + (size_t)(p0 + am) * (R * D) + k0 + kh;
        float4 a0 = *(const float4*)ga;
        float4 a1 = *(const float4*)(ga + 4);
        float4 a2 = *(const float4*)(ga + 8);
        float4 a3 = *(const float4*)(ga + 12);
        const float* gb = Wb + (size_t)(k0 + bk) * D + bn;
        float4 bb0 = *(const float4*)gb;
        float4 bb1 = *(const float4*)(gb + 4);
        float4 bb2 = *(const float4*)(gb + 8);
        float4 bb3 = *(const float4*)(gb + 12);
        float4 bb4 = *(const float4*)(gb + 16);
        float4 bb5 = *(const float4*)(gb + 20);
        float4 bb6 = *(const float4*)(gb + 24);
        float4 bb7 = *(const float4*)(gb + 28);

        if (t) __syncthreads();   // previous stage's compute done
        As[kh + 0][am] = a0.x;  As[kh + 1][am] = a0.y;
        As[kh + 2][am] = a0.z;  As[kh + 3][am] = a0.w;
        As[kh + 4][am] = a1.x;  As[kh + 5][am] = a1.y;
        As[kh + 6][am] = a1.z;  As[kh + 7][am] = a1.w;
        As[kh + 8][am] = a2.x;  As[kh + 9][am] = a2.y;
        As[kh + 10][am] = a2.z; As[kh + 11][am] = a2.w;
        As[kh + 12][am] = a3.x; As[kh + 13][am] = a3.y;
        As[kh + 14][am] = a3.z; As[kh + 15][am] = a3.w;
        *(float4*)&Bs[bk][bn]      = bb0;
        *(float4*)&Bs[bk][bn + 4]  = bb1;
        *(float4*)&Bs[bk][bn + 8]  = bb2;
        *(float4*)&Bs[bk][bn + 12] = bb3;
        *(float4*)&Bs[bk][bn + 16] = bb4;
        *(float4*)&Bs[bk][bn + 20] = bb5;
        *(float4*)&Bs[bk][bn + 24] = bb6;
        *(float4*)&Bs[bk][bn + 28] = bb7;
        __syncthreads();

#pragma unroll 8
        for (int k = 0; k < GKT; k++) {
            float4 fa0 = *(const float4*)&As[k][tm];       // broadcast loads
            float4 fa1 = *(const float4*)&As[k][tm + 4];
            ulonglong2 b01 = *(const ulonglong2*)&Bs[k][tn];
            ulonglong2 b23 = *(const ulonglong2*)&Bs[k][tn + 4];
            float av[8] = {fa0.x, fa0.y, fa0.z, fa0.w,
                           fa1.x, fa1.y, fa1.z, fa1.w};
#pragma unroll
            for (int mi = 0; mi < 8; mi++) {
                unsigned long long ap;
                asm("mov.b64 %0, {%1, %2};" : "=l"(ap) : "f"(av[mi]), "f"(av[mi]));
                asm("fma.rn.f32x2 %0, %1, %2, %0;" : "+l"(acc[mi][0]) : "l"(ap), "l"(b01.x));
                asm("fma.rn.f32x2 %0, %1, %2, %0;" : "+l"(acc[mi][1]) : "l"(ap), "l"(b01.y));
                asm("fma.rn.f32x2 %0, %1, %2, %0;" : "+l"(acc[mi][2]) : "l"(ap), "l"(b23.x));
                asm("fma.rn.f32x2 %0, %1, %2, %0;" : "+l"(acc[mi][3]) : "l"(ap), "l"(b23.y));
            }
        }
    }

    // write fp32 partials
    float* dst_base = g_part + (size_t)ks * PD;
#pragma unroll
    for (int mi = 0; mi < 8; mi++) {
        float c[8];
#pragma unroll
        for (int j = 0; j < 4; j++) {
            float lo, hi;
            asm("mov.b64 {%0, %1}, %2;" : "=f"(lo), "=f"(hi) : "l"(acc[mi][j]));
            c[2 * j] = lo;
            c[2 * j + 1] = hi;
        }
        float* dst = dst_base + (size_t)(p0 + tm + mi) * D + tn;
        *(float4*)dst       = make_float4(c[0], c[1], c[2], c[3]);
        *(float4*)(dst + 4) = make_float4(c[4], c[5], c[6], c[7]);
    }
}

// ---------------------------------------------------------------------------
// Kernel 5: reduce split-K partials + bias + sigmoid. grid=1024 x 128,
// one float4 per thread.
// ---------------------------------------------------------------------------
__global__ __launch_bounds__(128) void reduce_kernel(float* __restrict__ out) {
    int idx = blockIdx.x * 128 + threadIdx.x;   // float4 index
    int off = idx * 4;
    float4 a = *(const float4*)(g_part + off);
#pragma unroll
    for (int ks = 1; ks < KSPLIT; ks++) {
        float4 b = *(const float4*)(g_part + (size_t)ks * PD + off);
        a.x += b.x; a.y += b.y; a.z += b.z; a.w += b.w;
    }
    float4 bias = *(const float4*)&g_bias2[off & (D - 1)];
    a.x = 0.125f * (a.x + bias.x);
    a.y = 0.125f * (a.y + bias.y);
    a.z = 0.125f * (a.z + bias.z);
    a.w = 0.125f * (a.w + bias.w);
    a.x = __fdividef(1.f, 1.f + __expf(-a.x));
    a.y = __fdividef(1.f, 1.f + __expf(-a.y));
    a.z = __fdividef(1.f, 1.f + __expf(-a.z));
    a.w = __fdividef(1.f, 1.f + __expf(-a.w));
    *(float4*)(out + off) = a;
}

// ---------------------------------------------------------------------------
// Launch
// ---------------------------------------------------------------------------
extern "C" void kernel_launch(void* const* d_in, const int* in_sizes, int n_in,
                              void* d_out, int out_size) {
    const float* node_embeds   = (const float*)d_in[0];
    const int*   node_pairs    = (const int*)d_in[1];
    const int*   node_type_ids = (const int*)d_in[2];
    const int*   neighbor_idx  = (const int*)d_in[3];
    const float* delta_t       = (const float*)d_in[4];
    const float* W_phi         = (const float*)d_in[5];
    const float* W_zeta        = (const float*)d_in[6];
    const float* W_beta_w      = (const float*)d_in[7];
    const float* W_beta_b      = (const float*)d_in[8];
    float* out = (float*)d_out;

    prep_kernel<<<4, 128>>>(W_phi, W_zeta, W_beta_b);
    es_kernel<<<(P * 2) / 4, 128>>>(node_embeds, node_pairs, node_type_ids);
    main_kernel<<<P, 128>>>(node_embeds, node_type_ids, neighbor_idx, delta_t);
    gemm_kernel<<<(P / GM) * KSPLIT, 128>>>(W_beta_w);
    reduce_kernel<<<(PD / 4) / 128, 128>>>(out);
}